// round 6
// baseline (speedup 1.0000x reference)
#include <cuda_runtime.h>
#include <cuda_bf16.h>

// ---------------- problem constants (fixed shapes) ----------------
constexpr int kT   = 2048;
constexpr int kB   = 8;
constexpr int kD   = 1024;
constexpr int kHD  = 64;     // d
constexpr int kNM  = 8;
constexpr int kMP1 = 9;      // NM + 1
constexpr int kNTOK = kT * kB;          // 16384
constexpr int kNSEG = kB * kMP1;        // 72
constexpr int kSEGCAP = kT;             // max tokens per (b,m) segment
constexpr int kCH = 64;                 // chunk length
constexpr int kMAXCH = kSEGCAP / kCH;   // 32
constexpr int kWKSTRIDE = kMP1 * kHD;   // 576

// ---------------- static device scratch (no runtime alloc) ----------------
__device__ int   d_gidx[kNTOK * 2];
__device__ float d_galpha[kNTOK * 2];
__device__ int   d_segtok[kNSEG * kSEGCAP];
__device__ float d_segalpha[kNSEG * kSEGCAP];
__device__ int   d_segcnt[kNSEG];
__device__ float d_Q[(size_t)kNTOK * kHD];
__device__ float d_K[(size_t)kNSEG * kSEGCAP * kHD];
__device__ float d_V[(size_t)kNSEG * kSEGCAP * kHD];
__device__ float d_CS[(size_t)kNSEG * kMAXCH * kHD * kHD]; // S then (in-place) M_start

// ---------------- small helpers ----------------
__device__ __forceinline__ void outer4x4(float acc[4][4], float4 a, float4 b) {
    float av[4] = {a.x, a.y, a.z, a.w};
    float bv[4] = {b.x, b.y, b.z, b.w};
#pragma unroll
    for (int i = 0; i < 4; i++)
#pragma unroll
        for (int j = 0; j < 4; j++) acc[i][j] += av[i] * bv[j];
}

__device__ __forceinline__ float dot4(float4 a, float4 b) {
    return a.x * b.x + a.y * b.y + a.z * b.z + a.w * b.w;
}

// acc[i][j] += sum_u a[i].comp(u) * b[u].comp(j)
__device__ __forceinline__ void gemm4x4(float acc[4][4], const float4 a[4], const float4 b[4]) {
#pragma unroll
    for (int i = 0; i < 4; i++) {
        float av[4] = {a[i].x, a[i].y, a[i].z, a[i].w};
#pragma unroll
        for (int u = 0; u < 4; u++) {
            float bu[4] = {b[u].x, b[u].y, b[u].z, b[u].w};
#pragma unroll
            for (int j = 0; j < 4; j++) acc[i][j] += av[u] * bu[j];
        }
    }
}

// ---------------- kernel 0: zero output ----------------
__global__ void k_zero(float4* __restrict__ out) {
    out[blockIdx.x * 256 + threadIdx.x] = make_float4(0.f, 0.f, 0.f, 0.f);
}

// ---------------- kernel 1: gating (logits -> top2 -> 2-way softmax) ----------------
__global__ __launch_bounds__(256) void k_gate(const float* __restrict__ X,
                                              const float* __restrict__ Wg,
                                              const float* __restrict__ bg) {
    int n = blockIdx.x, tid = threadIdx.x;
    float acc[8] = {0.f, 0.f, 0.f, 0.f, 0.f, 0.f, 0.f, 0.f};
    const float* xr = X + (size_t)n * kD;
    for (int dd = tid; dd < kD; dd += 256) {
        float x = xr[dd];
        float4 w0 = *(const float4*)(Wg + dd * 8);
        float4 w1 = *(const float4*)(Wg + dd * 8 + 4);
        acc[0] += x * w0.x; acc[1] += x * w0.y; acc[2] += x * w0.z; acc[3] += x * w0.w;
        acc[4] += x * w1.x; acc[5] += x * w1.y; acc[6] += x * w1.z; acc[7] += x * w1.w;
    }
    __shared__ float red[8][256];
#pragma unroll
    for (int j = 0; j < 8; j++) red[j][tid] = acc[j];
    __syncthreads();
    for (int s = 128; s > 0; s >>= 1) {
        if (tid < s) {
#pragma unroll
            for (int j = 0; j < 8; j++) red[j][tid] += red[j][tid + s];
        }
        __syncthreads();
    }
    if (tid == 0) {
        float l[8];
#pragma unroll
        for (int j = 0; j < 8; j++) l[j] = red[j][0] + bg[j];
        int i1 = 0;
#pragma unroll
        for (int j = 1; j < 8; j++) if (l[j] > l[i1]) i1 = j;
        int i2 = -1; float best = -1e30f;
#pragma unroll
        for (int j = 0; j < 8; j++) if (j != i1 && l[j] > best) { best = l[j]; i2 = j; }
        float e = expf(l[i2] - l[i1]);         // <= 1
        float a1 = 1.0f / (1.0f + e);
        d_gidx[2 * n]     = i1 + 1;
        d_gidx[2 * n + 1] = i2 + 1;
        d_galpha[2 * n]     = a1;
        d_galpha[2 * n + 1] = e * a1;
    }
}

// ---------------- kernel 2: build per-(b,m) token lists (stable, time order) ----------------
__global__ void k_segbuild() {
    int seg = blockIdx.x;
    int b = seg / kMP1, m = seg % kMP1;
    int lane = threadIdx.x;
    int base = seg * kSEGCAP;
    if (m == 0) {
        for (int p = lane; p < kT; p += 32) {
            d_segtok[base + p] = p;
            d_segalpha[base + p] = 1.0f;
        }
        if (lane == 0) d_segcnt[seg] = kT;
        return;
    }
    int cnt = 0;
    for (int t0 = 0; t0 < kT; t0 += 32) {
        int t = t0 + lane;
        int n = t * kB + b;
        int i1 = d_gidx[2 * n], i2 = d_gidx[2 * n + 1];
        bool pred = (i1 == m) || (i2 == m);
        unsigned mask = __ballot_sync(0xffffffffu, pred);
        int rank = __popc(mask & ((1u << lane) - 1u));
        if (pred) {
            int pos = cnt + rank;
            d_segtok[base + pos] = t;
            d_segalpha[base + pos] = (i1 == m) ? d_galpha[2 * n] : d_galpha[2 * n + 1];
        }
        cnt += __popc(mask);
    }
    if (lane == 0) d_segcnt[seg] = cnt;
}

// ---------------- kernel 3: Q projection (dense 16384x1024x64 GEMM) ----------------
__global__ __launch_bounds__(256) void k_qproj(const float* __restrict__ X,
                                               const float* __restrict__ Wq,
                                               const float* __restrict__ bq) {
    __shared__ float Xs[32 * 64];   // [kk][row]
    __shared__ float Ws[32 * 64];   // [kk][col]
    int tid = threadIdx.x;
    int ty = tid >> 4, tx = tid & 15;
    int r0 = ty * 4, c0 = tx * 4;
    int rowBase = blockIdx.x * 64;
    float acc[4][4] = {};
    for (int dd0 = 0; dd0 < kD; dd0 += 32) {
#pragma unroll
        for (int it = 0; it < 2; it++) {
            int idx = it * 256 + tid;
            int row = idx >> 3, kq = (idx & 7) * 4;
            float4 xv = *(const float4*)(X + (size_t)(rowBase + row) * kD + dd0 + kq);
            Xs[(kq + 0) * 64 + row] = xv.x;
            Xs[(kq + 1) * 64 + row] = xv.y;
            Xs[(kq + 2) * 64 + row] = xv.z;
            Xs[(kq + 3) * 64 + row] = xv.w;
            int kk = idx >> 4, j4 = (idx & 15) * 4;
            *(float4*)&Ws[kk * 64 + j4] = *(const float4*)(Wq + (size_t)(dd0 + kk) * kHD + j4);
        }
        __syncthreads();
#pragma unroll 8
        for (int kk = 0; kk < 32; kk++) {
            float4 xv = *(float4*)&Xs[kk * 64 + r0];
            float4 wv = *(float4*)&Ws[kk * 64 + c0];
            outer4x4(acc, xv, wv);
        }
        __syncthreads();
    }
    float4 bb = *(const float4*)(bq + c0);
    float bv[4] = {bb.x, bb.y, bb.z, bb.w};
#pragma unroll
    for (int a = 0; a < 4; a++) {
        int n = rowBase + r0 + a;
        float4 o = make_float4(acc[a][0] + bv[0], acc[a][1] + bv[1],
                               acc[a][2] + bv[2], acc[a][3] + bv[3]);
        *(float4*)&d_Q[(size_t)n * kHD + c0] = o;
    }
}

// ---------------- kernel 4: gathered K/V projections per segment ----------------
__global__ __launch_bounds__(256) void k_kvproj(const float* __restrict__ X,
                                                const float* __restrict__ Wk,
                                                const float* __restrict__ bk,
                                                const float* __restrict__ Wv,
                                                const float* __restrict__ bv) {
    int seg = blockIdx.y;
    int cnt = d_segcnt[seg];
    int tileBase = blockIdx.x * 64;
    if (tileBase >= cnt) return;
    int L = min(64, cnt - tileBase);
    int b = seg / kMP1, m = seg % kMP1;

    __shared__ float Xs[32 * 64];    // [kk][row]
    __shared__ float Wks[32 * 64];   // [kk][col]
    __shared__ float Wvs[32 * 64];
    __shared__ int rowN[64];

    int tid = threadIdx.x;
    int ty = tid >> 4, tx = tid & 15;
    int r0 = ty * 4, c0 = tx * 4;

    if (tid < 64) {
        int n = -1;
        if (tid < L) {
            int t = d_segtok[seg * kSEGCAP + tileBase + tid];
            n = t * kB + b;
        }
        rowN[tid] = n;
    }
    __syncthreads();

    float accK[4][4] = {}, accV[4][4] = {};
    const float* WkBase = Wk + m * kHD;
    const float* WvBase = Wv + m * kHD;

    for (int dd0 = 0; dd0 < kD; dd0 += 32) {
#pragma unroll
        for (int it = 0; it < 2; it++) {
            int idx = it * 256 + tid;
            int row = idx >> 3, kq = (idx & 7) * 4;
            float4 xv = make_float4(0.f, 0.f, 0.f, 0.f);
            int n = rowN[row];
            if (n >= 0) xv = *(const float4*)(X + (size_t)n * kD + dd0 + kq);
            Xs[(kq + 0) * 64 + row] = xv.x;
            Xs[(kq + 1) * 64 + row] = xv.y;
            Xs[(kq + 2) * 64 + row] = xv.z;
            Xs[(kq + 3) * 64 + row] = xv.w;
            int kk = idx >> 4, j4 = (idx & 15) * 4;
            *(float4*)&Wks[kk * 64 + j4] =
                *(const float4*)(WkBase + (size_t)(dd0 + kk) * kWKSTRIDE + j4);
            *(float4*)&Wvs[kk * 64 + j4] =
                *(const float4*)(WvBase + (size_t)(dd0 + kk) * kWKSTRIDE + j4);
        }
        __syncthreads();
#pragma unroll 4
        for (int kk = 0; kk < 32; kk++) {
            float4 xv = *(float4*)&Xs[kk * 64 + r0];
            float4 wk = *(float4*)&Wks[kk * 64 + c0];
            float4 wv = *(float4*)&Wvs[kk * 64 + c0];
            outer4x4(accK, xv, wk);
            outer4x4(accV, xv, wv);
        }
        __syncthreads();
    }

    float4 bk4 = *(const float4*)(bk + m * kHD + c0);
    float4 bv4 = *(const float4*)(bv + m * kHD + c0);
    float bka[4] = {bk4.x, bk4.y, bk4.z, bk4.w};
    float bva[4] = {bv4.x, bv4.y, bv4.z, bv4.w};
#pragma unroll
    for (int a = 0; a < 4; a++) {
        int r = r0 + a;
        if (r < L) {
            size_t p = ((size_t)seg * kSEGCAP + tileBase + r) * kHD + c0;
            float4 ok = make_float4(accK[a][0] + bka[0], accK[a][1] + bka[1],
                                    accK[a][2] + bka[2], accK[a][3] + bka[3]);
            float4 ov = make_float4(accV[a][0] + bva[0], accV[a][1] + bva[1],
                                    accV[a][2] + bva[2], accV[a][3] + bva[3]);
            *(float4*)&d_K[p] = ok;
            *(float4*)&d_V[p] = ov;
        }
    }
}

// ---------------- kernel 5: per-chunk S = K^T V ----------------
__global__ __launch_bounds__(256) void k_chunkS() {
    int seg = blockIdx.y, c = blockIdx.x;
    int cnt = d_segcnt[seg];
    if (c * kCH >= cnt) return;
    int L = min(kCH, cnt - c * kCH);

    __shared__ float Ks[64 * 64];   // [r][i]
    __shared__ float Vs[64 * 64];   // [r][j]
    int tid = threadIdx.x;
    int ty = tid >> 4, tx = tid & 15;
    int i0 = ty * 4, j0 = tx * 4;
    size_t rowBase = (size_t)seg * kSEGCAP + c * kCH;

#pragma unroll
    for (int it = 0; it < 4; it++) {
        int idx = it * 256 + tid;
        int r = idx >> 4, j4 = (idx & 15) * 4;
        float4 kv = make_float4(0.f, 0.f, 0.f, 0.f), vv = kv;
        if (r < L) {
            kv = *(const float4*)&d_K[(rowBase + r) * kHD + j4];
            vv = *(const float4*)&d_V[(rowBase + r) * kHD + j4];
        }
        *(float4*)&Ks[r * 64 + j4] = kv;
        *(float4*)&Vs[r * 64 + j4] = vv;
    }
    __syncthreads();

    float acc[4][4] = {};
#pragma unroll 8
    for (int r = 0; r < 64; r++) {
        float4 kv = *(float4*)&Ks[r * 64 + i0];
        float4 vv = *(float4*)&Vs[r * 64 + j0];
        outer4x4(acc, kv, vv);
    }

    float* Sp = &d_CS[(size_t)(seg * kMAXCH + c) * 4096];
#pragma unroll
    for (int a = 0; a < 4; a++) {
        float4 o = make_float4(acc[a][0], acc[a][1], acc[a][2], acc[a][3]);
        *(float4*)&Sp[(i0 + a) * 64 + j0] = o;
    }
}

// ---------------- kernel 6: sequential prefix over chunks -> M_start (in place) ----------------
__global__ __launch_bounds__(256) void k_prefix(const float* __restrict__ M0) {
    int seg = blockIdx.x, tid = threadIdx.x;
    int cnt = d_segcnt[seg];
    int nc = (cnt + kCH - 1) / kCH;
    float run[16];
#pragma unroll
    for (int q = 0; q < 16; q++) run[q] = M0[q * 256 + tid];
    for (int c = 0; c < nc; c++) {
        float* p = &d_CS[(size_t)(seg * kMAXCH + c) * 4096];
#pragma unroll
        for (int q = 0; q < 16; q++) {
            float s = p[q * 256 + tid];
            p[q * 256 + tid] = run[q];   // M_start for this chunk
            run[q] += s;
        }
    }
}

// ---------------- kernel 7: O = tril(QK^T)V + Q M_start, weighted scatter ----------------
__global__ __launch_bounds__(256) void k_out(float* __restrict__ out) {
    int seg = blockIdx.y, c = blockIdx.x;
    int cnt = d_segcnt[seg];
    if (c * kCH >= cnt) return;
    int b = seg / kMP1;

    __shared__ float Qs[64 * 64];   // [r][j]
    __shared__ float KA[64 * 64];   // K [r][j], then masked A [r][cc]
    __shared__ float Vs[64 * 64];   // [r][j]

    int tid = threadIdx.x;
    int ty = tid >> 4, tx = tid & 15;
    int r0 = ty * 4;
    size_t rowBase = (size_t)seg * kSEGCAP + c * kCH;
    int segBase = seg * kSEGCAP;

#pragma unroll
    for (int it = 0; it < 4; it++) {
        int idx = it * 256 + tid;
        int r = idx >> 4, j4 = (idx & 15) * 4;
        float4 qv = make_float4(0.f, 0.f, 0.f, 0.f), kv = qv, vv = qv;
        int pos = c * kCH + r;
        if (pos < cnt) {
            int t = d_segtok[segBase + pos];
            int n = t * kB + b;
            qv = *(const float4*)&d_Q[(size_t)n * kHD + j4];
            kv = *(const float4*)&d_K[(rowBase + r) * kHD + j4];
            vv = *(const float4*)&d_V[(rowBase + r) * kHD + j4];
        }
        *(float4*)&Qs[r * 64 + j4] = qv;
        *(float4*)&KA[r * 64 + j4] = kv;
        *(float4*)&Vs[r * 64 + j4] = vv;
    }
    __syncthreads();

    // Phase A: A[r][cc] = Q[r] . K[cc]
    int cc0 = tx * 4;
    float aacc[4][4] = {};
#pragma unroll 4
    for (int j = 0; j < 64; j += 4) {
        float4 q[4], k[4];
#pragma unroll
        for (int a = 0; a < 4; a++) q[a] = *(float4*)&Qs[(r0 + a) * 64 + j];
#pragma unroll
        for (int u = 0; u < 4; u++) k[u] = *(float4*)&KA[(cc0 + u) * 64 + j];
#pragma unroll
        for (int a = 0; a < 4; a++)
#pragma unroll
            for (int u = 0; u < 4; u++) aacc[a][u] += dot4(q[a], k[u]);
    }
    __syncthreads();
    // write masked (inclusive lower-triangular) A over KA
#pragma unroll
    for (int a = 0; a < 4; a++) {
        int r = r0 + a;
#pragma unroll
        for (int u = 0; u < 4; u++) {
            int cc = cc0 + u;
            KA[r * 64 + cc] = (cc <= r) ? aacc[a][u] : 0.f;
        }
    }
    __syncthreads();

    // Phase O: O = A V + Q M_start
    int j0 = tx * 4;
    float oacc[4][4] = {};
#pragma unroll 4
    for (int cc = 0; cc < 64; cc += 4) {
        float4 arow[4], vrow[4];
#pragma unroll
        for (int a = 0; a < 4; a++) arow[a] = *(float4*)&KA[(r0 + a) * 64 + cc];
#pragma unroll
        for (int u = 0; u < 4; u++) vrow[u] = *(float4*)&Vs[(cc + u) * 64 + j0];
        gemm4x4(oacc, arow, vrow);
    }
    const float* Mg = &d_CS[(size_t)(seg * kMAXCH + c) * 4096];
#pragma unroll 4
    for (int i = 0; i < 64; i += 4) {
        float4 qrow[4], mrow[4];
#pragma unroll
        for (int a = 0; a < 4; a++) qrow[a] = *(float4*)&Qs[(r0 + a) * 64 + i];
#pragma unroll
        for (int u = 0; u < 4; u++) mrow[u] = *(const float4*)&Mg[(i + u) * 64 + j0];
        gemm4x4(oacc, qrow, mrow);
    }

    // scatter: out[t,b,:] += alpha * O[r,:]
#pragma unroll
    for (int a = 0; a < 4; a++) {
        int r = r0 + a;
        int pos = c * kCH + r;
        if (pos < cnt) {
            int t = d_segtok[segBase + pos];
            float al = d_segalpha[segBase + pos];
            float* op = out + ((size_t)t * kB + b) * kHD + j0;
            atomicAdd(op + 0, al * oacc[a][0]);
            atomicAdd(op + 1, al * oacc[a][1]);
            atomicAdd(op + 2, al * oacc[a][2]);
            atomicAdd(op + 3, al * oacc[a][3]);
        }
    }
}

// ---------------- launch ----------------
extern "C" void kernel_launch(void* const* d_in, const int* in_sizes, int n_in,
                              void* d_out, int out_size) {
    const float* X  = (const float*)d_in[0];
    const float* M0 = (const float*)d_in[1];
    const float* Wq = (const float*)d_in[2];
    const float* bq = (const float*)d_in[3];
    const float* Wk = (const float*)d_in[4];
    const float* bk = (const float*)d_in[5];
    const float* Wv = (const float*)d_in[6];
    const float* bv = (const float*)d_in[7];
    const float* Wg = (const float*)d_in[8];
    const float* bg = (const float*)d_in[9];
    float* out = (float*)d_out;

    k_zero<<<kNTOK * kHD / (256 * 4), 256>>>((float4*)out);
    k_gate<<<kNTOK, 256>>>(X, Wg, bg);
    k_segbuild<<<kNSEG, 32>>>();
    k_qproj<<<kNTOK / 64, 256>>>(X, Wq, bq);
    k_kvproj<<<dim3(kMAXCH, kNSEG), 256>>>(X, Wk, bk, Wv, bv);
    k_chunkS<<<dim3(kMAXCH, kNSEG), 256>>>();
    k_prefix<<<kNSEG, 256>>>(M0);
    k_out<<<dim3(kMAXCH, kNSEG), 256>>>(out);
}

// round 10
// speedup vs baseline: 1.0038x; 1.0038x over previous
#include <cuda_runtime.h>
#include <cuda_bf16.h>

// ---------------- problem constants (fixed shapes) ----------------
constexpr int kT   = 2048;
constexpr int kB   = 8;
constexpr int kD   = 1024;
constexpr int kHD  = 64;     // d
constexpr int kNM  = 8;
constexpr int kMP1 = 9;      // NM + 1
constexpr int kNTOK = kT * kB;          // 16384
constexpr int kNSEG = kB * kMP1;        // 72
constexpr int kSEGCAP = kT;             // max tokens per (b,m) segment
constexpr int kCH = 64;                 // chunk length
constexpr int kMAXCH = kSEGCAP / kCH;   // 32
constexpr int kWKSTRIDE = kMP1 * kHD;   // 576

// ---------------- static device scratch (no runtime alloc) ----------------
__device__ int   d_gidx[kNTOK * 2];
__device__ float d_galpha[kNTOK * 2];
__device__ int   d_segtok[kNSEG * kSEGCAP];
__device__ float d_segalpha[kNSEG * kSEGCAP];
__device__ int   d_segcnt[kNSEG];
__device__ float d_Q[(size_t)kNTOK * kHD];
__device__ float d_K[(size_t)kNSEG * kSEGCAP * kHD];
__device__ float d_V[(size_t)kNSEG * kSEGCAP * kHD];
__device__ float d_CS[(size_t)kNSEG * kMAXCH * kHD * kHD]; // S then (in-place) M_start

// ---------------- small helpers ----------------
__device__ __forceinline__ void outer4x4(float acc[4][4], float4 a, float4 b) {
    float av[4] = {a.x, a.y, a.z, a.w};
    float bv[4] = {b.x, b.y, b.z, b.w};
#pragma unroll
    for (int i = 0; i < 4; i++)
#pragma unroll
        for (int j = 0; j < 4; j++) acc[i][j] += av[i] * bv[j];
}

__device__ __forceinline__ float dot4(float4 a, float4 b) {
    return a.x * b.x + a.y * b.y + a.z * b.z + a.w * b.w;
}

// acc[i][j] += sum_u a[i].comp(u) * b[u].comp(j)
__device__ __forceinline__ void gemm4x4(float acc[4][4], const float4 a[4], const float4 b[4]) {
#pragma unroll
    for (int i = 0; i < 4; i++) {
        float av[4] = {a[i].x, a[i].y, a[i].z, a[i].w};
#pragma unroll
        for (int u = 0; u < 4; u++) {
            float bu[4] = {b[u].x, b[u].y, b[u].z, b[u].w};
#pragma unroll
            for (int j = 0; j < 4; j++) acc[i][j] += av[u] * bu[j];
        }
    }
}

// ---------------- kernel 0: zero output ----------------
__global__ void k_zero(float4* __restrict__ out) {
    out[blockIdx.x * 256 + threadIdx.x] = make_float4(0.f, 0.f, 0.f, 0.f);
}

// ---------------- kernel 1: gating (logits -> top2 -> 2-way softmax) ----------------
__global__ __launch_bounds__(256) void k_gate(const float* __restrict__ X,
                                              const float* __restrict__ Wg,
                                              const float* __restrict__ bg) {
    int n = blockIdx.x, tid = threadIdx.x;
    float acc[8] = {0.f, 0.f, 0.f, 0.f, 0.f, 0.f, 0.f, 0.f};
    const float* xr = X + (size_t)n * kD;
    for (int dd = tid; dd < kD; dd += 256) {
        float x = xr[dd];
        float4 w0 = *(const float4*)(Wg + dd * 8);
        float4 w1 = *(const float4*)(Wg + dd * 8 + 4);
        acc[0] += x * w0.x; acc[1] += x * w0.y; acc[2] += x * w0.z; acc[3] += x * w0.w;
        acc[4] += x * w1.x; acc[5] += x * w1.y; acc[6] += x * w1.z; acc[7] += x * w1.w;
    }
    __shared__ float red[8][256];
#pragma unroll
    for (int j = 0; j < 8; j++) red[j][tid] = acc[j];
    __syncthreads();
    for (int s = 128; s > 0; s >>= 1) {
        if (tid < s) {
#pragma unroll
            for (int j = 0; j < 8; j++) red[j][tid] += red[j][tid + s];
        }
        __syncthreads();
    }
    if (tid == 0) {
        float l[8];
#pragma unroll
        for (int j = 0; j < 8; j++) l[j] = red[j][0] + bg[j];
        int i1 = 0;
#pragma unroll
        for (int j = 1; j < 8; j++) if (l[j] > l[i1]) i1 = j;
        int i2 = -1; float best = -1e30f;
#pragma unroll
        for (int j = 0; j < 8; j++) if (j != i1 && l[j] > best) { best = l[j]; i2 = j; }
        float e = expf(l[i2] - l[i1]);         // <= 1
        float a1 = 1.0f / (1.0f + e);
        d_gidx[2 * n]     = i1 + 1;
        d_gidx[2 * n + 1] = i2 + 1;
        d_galpha[2 * n]     = a1;
        d_galpha[2 * n + 1] = e * a1;
    }
}

// ---------------- kernel 2: build per-(b,m) token lists (stable, time order) ----------------
__global__ void k_segbuild() {
    int seg = blockIdx.x;
    int b = seg / kMP1, m = seg % kMP1;
    int lane = threadIdx.x;
    int base = seg * kSEGCAP;
    if (m == 0) {
        for (int p = lane; p < kT; p += 32) {
            d_segtok[base + p] = p;
            d_segalpha[base + p] = 1.0f;
        }
        if (lane == 0) d_segcnt[seg] = kT;
        return;
    }
    int cnt = 0;
    for (int t0 = 0; t0 < kT; t0 += 32) {
        int t = t0 + lane;
        int n = t * kB + b;
        int i1 = d_gidx[2 * n], i2 = d_gidx[2 * n + 1];
        bool pred = (i1 == m) || (i2 == m);
        unsigned mask = __ballot_sync(0xffffffffu, pred);
        int rank = __popc(mask & ((1u << lane) - 1u));
        if (pred) {
            int pos = cnt + rank;
            d_segtok[base + pos] = t;
            d_segalpha[base + pos] = (i1 == m) ? d_galpha[2 * n] : d_galpha[2 * n + 1];
        }
        cnt += __popc(mask);
    }
    if (lane == 0) d_segcnt[seg] = cnt;
}

// ---------------- kernel 3: Q projection (dense 16384x1024x64 GEMM) ----------------
__global__ __launch_bounds__(256) void k_qproj(const float* __restrict__ X,
                                               const float* __restrict__ Wq,
                                               const float* __restrict__ bq) {
    __shared__ float Xs[32 * 64];   // [kk][row]
    __shared__ float Ws[32 * 64];   // [kk][col]
    int tid = threadIdx.x;
    int ty = tid >> 4, tx = tid & 15;
    int r0 = ty * 4, c0 = tx * 4;
    int rowBase = blockIdx.x * 64;
    float acc[4][4] = {};
    for (int dd0 = 0; dd0 < kD; dd0 += 32) {
#pragma unroll
        for (int it = 0; it < 2; it++) {
            int idx = it * 256 + tid;
            int row = idx >> 3, kq = (idx & 7) * 4;
            float4 xv = *(const float4*)(X + (size_t)(rowBase + row) * kD + dd0 + kq);
            Xs[(kq + 0) * 64 + row] = xv.x;
            Xs[(kq + 1) * 64 + row] = xv.y;
            Xs[(kq + 2) * 64 + row] = xv.z;
            Xs[(kq + 3) * 64 + row] = xv.w;
            int kk = idx >> 4, j4 = (idx & 15) * 4;
            *(float4*)&Ws[kk * 64 + j4] = *(const float4*)(Wq + (size_t)(dd0 + kk) * kHD + j4);
        }
        __syncthreads();
#pragma unroll 8
        for (int kk = 0; kk < 32; kk++) {
            float4 xv = *(float4*)&Xs[kk * 64 + r0];
            float4 wv = *(float4*)&Ws[kk * 64 + c0];
            outer4x4(acc, xv, wv);
        }
        __syncthreads();
    }
    float4 bb = *(const float4*)(bq + c0);
    float bv[4] = {bb.x, bb.y, bb.z, bb.w};
#pragma unroll
    for (int a = 0; a < 4; a++) {
        int n = rowBase + r0 + a;
        float4 o = make_float4(acc[a][0] + bv[0], acc[a][1] + bv[1],
                               acc[a][2] + bv[2], acc[a][3] + bv[3]);
        *(float4*)&d_Q[(size_t)n * kHD + c0] = o;
    }
}

// ---------------- kernel 4: gathered K/V projections per segment ----------------
__global__ __launch_bounds__(256) void k_kvproj(const float* __restrict__ X,
                                                const float* __restrict__ Wk,
                                                const float* __restrict__ bk,
                                                const float* __restrict__ Wv,
                                                const float* __restrict__ bv) {
    int seg = blockIdx.y;
    int cnt = d_segcnt[seg];
    int tileBase = blockIdx.x * 64;
    if (tileBase >= cnt) return;
    int L = min(64, cnt - tileBase);
    int b = seg / kMP1, m = seg % kMP1;

    __shared__ float Xs[32 * 64];    // [kk][row]
    __shared__ float Wks[32 * 64];   // [kk][col]
    __shared__ float Wvs[32 * 64];
    __shared__ int rowN[64];

    int tid = threadIdx.x;
    int ty = tid >> 4, tx = tid & 15;
    int r0 = ty * 4, c0 = tx * 4;

    if (tid < 64) {
        int n = -1;
        if (tid < L) {
            int t = d_segtok[seg * kSEGCAP + tileBase + tid];
            n = t * kB + b;
        }
        rowN[tid] = n;
    }
    __syncthreads();

    float accK[4][4] = {}, accV[4][4] = {};
    const float* WkBase = Wk + m * kHD;
    const float* WvBase = Wv + m * kHD;

    for (int dd0 = 0; dd0 < kD; dd0 += 32) {
#pragma unroll
        for (int it = 0; it < 2; it++) {
            int idx = it * 256 + tid;
            int row = idx >> 3, kq = (idx & 7) * 4;
            float4 xv = make_float4(0.f, 0.f, 0.f, 0.f);
            int n = rowN[row];
            if (n >= 0) xv = *(const float4*)(X + (size_t)n * kD + dd0 + kq);
            Xs[(kq + 0) * 64 + row] = xv.x;
            Xs[(kq + 1) * 64 + row] = xv.y;
            Xs[(kq + 2) * 64 + row] = xv.z;
            Xs[(kq + 3) * 64 + row] = xv.w;
            int kk = idx >> 4, j4 = (idx & 15) * 4;
            *(float4*)&Wks[kk * 64 + j4] =
                *(const float4*)(WkBase + (size_t)(dd0 + kk) * kWKSTRIDE + j4);
            *(float4*)&Wvs[kk * 64 + j4] =
                *(const float4*)(WvBase + (size_t)(dd0 + kk) * kWKSTRIDE + j4);
        }
        __syncthreads();
#pragma unroll 4
        for (int kk = 0; kk < 32; kk++) {
            float4 xv = *(float4*)&Xs[kk * 64 + r0];
            float4 wk = *(float4*)&Wks[kk * 64 + c0];
            float4 wv = *(float4*)&Wvs[kk * 64 + c0];
            outer4x4(accK, xv, wk);
            outer4x4(accV, xv, wv);
        }
        __syncthreads();
    }

    float4 bk4 = *(const float4*)(bk + m * kHD + c0);
    float4 bv4 = *(const float4*)(bv + m * kHD + c0);
    float bka[4] = {bk4.x, bk4.y, bk4.z, bk4.w};
    float bva[4] = {bv4.x, bv4.y, bv4.z, bv4.w};
#pragma unroll
    for (int a = 0; a < 4; a++) {
        int r = r0 + a;
        if (r < L) {
            size_t p = ((size_t)seg * kSEGCAP + tileBase + r) * kHD + c0;
            float4 ok = make_float4(accK[a][0] + bka[0], accK[a][1] + bka[1],
                                    accK[a][2] + bka[2], accK[a][3] + bka[3]);
            float4 ov = make_float4(accV[a][0] + bva[0], accV[a][1] + bva[1],
                                    accV[a][2] + bva[2], accV[a][3] + bva[3]);
            *(float4*)&d_K[p] = ok;
            *(float4*)&d_V[p] = ov;
        }
    }
}

// ---------------- kernel 5: per-chunk S = K^T V ----------------
__global__ __launch_bounds__(256) void k_chunkS() {
    int seg = blockIdx.y, c = blockIdx.x;
    int cnt = d_segcnt[seg];
    if (c * kCH >= cnt) return;
    int L = min(kCH, cnt - c * kCH);

    __shared__ float Ks[64 * 64];   // [r][i]
    __shared__ float Vs[64 * 64];   // [r][j]
    int tid = threadIdx.x;
    int ty = tid >> 4, tx = tid & 15;
    int i0 = ty * 4, j0 = tx * 4;
    size_t rowBase = (size_t)seg * kSEGCAP + c * kCH;

#pragma unroll
    for (int it = 0; it < 4; it++) {
        int idx = it * 256 + tid;
        int r = idx >> 4, j4 = (idx & 15) * 4;
        float4 kv = make_float4(0.f, 0.f, 0.f, 0.f), vv = kv;
        if (r < L) {
            kv = *(const float4*)&d_K[(rowBase + r) * kHD + j4];
            vv = *(const float4*)&d_V[(rowBase + r) * kHD + j4];
        }
        *(float4*)&Ks[r * 64 + j4] = kv;
        *(float4*)&Vs[r * 64 + j4] = vv;
    }
    __syncthreads();

    float acc[4][4] = {};
#pragma unroll 8
    for (int r = 0; r < 64; r++) {
        float4 kv = *(float4*)&Ks[r * 64 + i0];
        float4 vv = *(float4*)&Vs[r * 64 + j0];
        outer4x4(acc, kv, vv);
    }

    float* Sp = &d_CS[(size_t)(seg * kMAXCH + c) * 4096];
#pragma unroll
    for (int a = 0; a < 4; a++) {
        float4 o = make_float4(acc[a][0], acc[a][1], acc[a][2], acc[a][3]);
        *(float4*)&Sp[(i0 + a) * 64 + j0] = o;
    }
}

// ---------------- kernel 6: sequential prefix over chunks -> M_start (in place) ----------------
__global__ __launch_bounds__(256) void k_prefix(const float* __restrict__ M0) {
    int seg = blockIdx.x, tid = threadIdx.x;
    int cnt = d_segcnt[seg];
    int nc = (cnt + kCH - 1) / kCH;
    float run[16];
#pragma unroll
    for (int q = 0; q < 16; q++) run[q] = M0[q * 256 + tid];
    for (int c = 0; c < nc; c++) {
        float* p = &d_CS[(size_t)(seg * kMAXCH + c) * 4096];
#pragma unroll
        for (int q = 0; q < 16; q++) {
            float s = p[q * 256 + tid];
            p[q * 256 + tid] = run[q];   // M_start for this chunk
            run[q] += s;
        }
    }
}

// ---------------- kernel 7: O = tril(QK^T)V + Q M_start, weighted scatter ----------------
__global__ __launch_bounds__(256) void k_out(float* __restrict__ out) {
    int seg = blockIdx.y, c = blockIdx.x;
    int cnt = d_segcnt[seg];
    if (c * kCH >= cnt) return;
    int b = seg / kMP1;

    __shared__ float Qs[64 * 64];   // [r][j]
    __shared__ float KA[64 * 64];   // K [r][j], then masked A [r][cc]
    __shared__ float Vs[64 * 64];   // [r][j]

    int tid = threadIdx.x;
    int ty = tid >> 4, tx = tid & 15;
    int r0 = ty * 4;
    size_t rowBase = (size_t)seg * kSEGCAP + c * kCH;
    int segBase = seg * kSEGCAP;

#pragma unroll
    for (int it = 0; it < 4; it++) {
        int idx = it * 256 + tid;
        int r = idx >> 4, j4 = (idx & 15) * 4;
        float4 qv = make_float4(0.f, 0.f, 0.f, 0.f), kv = qv, vv = qv;
        int pos = c * kCH + r;
        if (pos < cnt) {
            int t = d_segtok[segBase + pos];
            int n = t * kB + b;
            qv = *(const float4*)&d_Q[(size_t)n * kHD + j4];
            kv = *(const float4*)&d_K[(rowBase + r) * kHD + j4];
            vv = *(const float4*)&d_V[(rowBase + r) * kHD + j4];
        }
        *(float4*)&Qs[r * 64 + j4] = qv;
        *(float4*)&KA[r * 64 + j4] = kv;
        *(float4*)&Vs[r * 64 + j4] = vv;
    }
    __syncthreads();

    // Phase A: A[r][cc] = Q[r] . K[cc]
    int cc0 = tx * 4;
    float aacc[4][4] = {};
#pragma unroll 4
    for (int j = 0; j < 64; j += 4) {
        float4 q[4], k[4];
#pragma unroll
        for (int a = 0; a < 4; a++) q[a] = *(float4*)&Qs[(r0 + a) * 64 + j];
#pragma unroll
        for (int u = 0; u < 4; u++) k[u] = *(float4*)&KA[(cc0 + u) * 64 + j];
#pragma unroll
        for (int a = 0; a < 4; a++)
#pragma unroll
            for (int u = 0; u < 4; u++) aacc[a][u] += dot4(q[a], k[u]);
    }
    __syncthreads();
    // write masked (inclusive lower-triangular) A over KA
#pragma unroll
    for (int a = 0; a < 4; a++) {
        int r = r0 + a;
#pragma unroll
        for (int u = 0; u < 4; u++) {
            int cc = cc0 + u;
            KA[r * 64 + cc] = (cc <= r) ? aacc[a][u] : 0.f;
        }
    }
    __syncthreads();

    // Phase O: O = A V + Q M_start
    int j0 = tx * 4;
    float oacc[4][4] = {};
#pragma unroll 4
    for (int cc = 0; cc < 64; cc += 4) {
        float4 arow[4], vrow[4];
#pragma unroll
        for (int a = 0; a < 4; a++) arow[a] = *(float4*)&KA[(r0 + a) * 64 + cc];
#pragma unroll
        for (int u = 0; u < 4; u++) vrow[u] = *(float4*)&Vs[(cc + u) * 64 + j0];
        gemm4x4(oacc, arow, vrow);
    }
    const float* Mg = &d_CS[(size_t)(seg * kMAXCH + c) * 4096];
#pragma unroll 4
    for (int i = 0; i < 64; i += 4) {
        float4 qrow[4], mrow[4];
#pragma unroll
        for (int a = 0; a < 4; a++) qrow[a] = *(float4*)&Qs[(r0 + a) * 64 + i];
#pragma unroll
        for (int u = 0; u < 4; u++) mrow[u] = *(const float4*)&Mg[(i + u) * 64 + j0];
        gemm4x4(oacc, qrow, mrow);
    }

    // scatter: out[t,b,:] += alpha * O[r,:]
#pragma unroll
    for (int a = 0; a < 4; a++) {
        int r = r0 + a;
        int pos = c * kCH + r;
        if (pos < cnt) {
            int t = d_segtok[segBase + pos];
            float al = d_segalpha[segBase + pos];
            float* op = out + ((size_t)t * kB + b) * kHD + j0;
            atomicAdd(op + 0, al * oacc[a][0]);
            atomicAdd(op + 1, al * oacc[a][1]);
            atomicAdd(op + 2, al * oacc[a][2]);
            atomicAdd(op + 3, al * oacc[a][3]);
        }
    }
}

// ---------------- launch ----------------
extern "C" void kernel_launch(void* const* d_in, const int* in_sizes, int n_in,
                              void* d_out, int out_size) {
    const float* X  = (const float*)d_in[0];
    const float* M0 = (const float*)d_in[1];
    const float* Wq = (const float*)d_in[2];
    const float* bq = (const float*)d_in[3];
    const float* Wk = (const float*)d_in[4];
    const float* bk = (const float*)d_in[5];
    const float* Wv = (const float*)d_in[6];
    const float* bv = (const float*)d_in[7];
    const float* Wg = (const float*)d_in[8];
    const float* bg = (const float*)d_in[9];
    float* out = (float*)d_out;

    k_zero<<<kNTOK * kHD / (256 * 4), 256>>>((float4*)out);
    k_gate<<<kNTOK, 256>>>(X, Wg, bg);
    k_segbuild<<<kNSEG, 32>>>();
    k_qproj<<<kNTOK / 64, 256>>>(X, Wq, bq);
    k_kvproj<<<dim3(kMAXCH, kNSEG), 256>>>(X, Wk, bk, Wv, bv);
    k_chunkS<<<dim3(kMAXCH, kNSEG), 256>>>();
    k_prefix<<<kNSEG, 256>>>(M0);
    k_out<<<dim3(kMAXCH, kNSEG), 256>>>(out);
}

// round 11
// speedup vs baseline: 1.0041x; 1.0003x over previous
#include <cuda_runtime.h>
#include <cuda_bf16.h>

// ---------------- problem constants (fixed shapes) ----------------
constexpr int kT   = 2048;
constexpr int kB   = 8;
constexpr int kD   = 1024;
constexpr int kHD  = 64;     // d
constexpr int kNM  = 8;
constexpr int kMP1 = 9;      // NM + 1
constexpr int kNTOK = kT * kB;          // 16384
constexpr int kNSEG = kB * kMP1;        // 72
constexpr int kSEGCAP = kT;             // max tokens per (b,m) segment
constexpr int kCH = 64;                 // chunk length
constexpr int kMAXCH = kSEGCAP / kCH;   // 32
constexpr int kWKSTRIDE = kMP1 * kHD;   // 576

// ---------------- static device scratch (no runtime alloc) ----------------
__device__ int   d_gidx[kNTOK * 2];
__device__ float d_galpha[kNTOK * 2];
__device__ int   d_segtok[kNSEG * kSEGCAP];
__device__ float d_segalpha[kNSEG * kSEGCAP];
__device__ int   d_segcnt[kNSEG];
__device__ float d_Q[(size_t)kNTOK * kHD];
__device__ float d_K[(size_t)kNSEG * kSEGCAP * kHD];
__device__ float d_V[(size_t)kNSEG * kSEGCAP * kHD];
__device__ float d_CS[(size_t)kNSEG * kMAXCH * kHD * kHD]; // S then (in-place) M_start

// ---------------- small helpers ----------------
__device__ __forceinline__ void outer4x4(float acc[4][4], float4 a, float4 b) {
    float av[4] = {a.x, a.y, a.z, a.w};
    float bv[4] = {b.x, b.y, b.z, b.w};
#pragma unroll
    for (int i = 0; i < 4; i++)
#pragma unroll
        for (int j = 0; j < 4; j++) acc[i][j] += av[i] * bv[j];
}

__device__ __forceinline__ float dot4(float4 a, float4 b) {
    return a.x * b.x + a.y * b.y + a.z * b.z + a.w * b.w;
}

// acc[i][j] += sum_u a[i].comp(u) * b[u].comp(j)
__device__ __forceinline__ void gemm4x4(float acc[4][4], const float4 a[4], const float4 b[4]) {
#pragma unroll
    for (int i = 0; i < 4; i++) {
        float av[4] = {a[i].x, a[i].y, a[i].z, a[i].w};
#pragma unroll
        for (int u = 0; u < 4; u++) {
            float bu[4] = {b[u].x, b[u].y, b[u].z, b[u].w};
#pragma unroll
            for (int j = 0; j < 4; j++) acc[i][j] += av[u] * bu[j];
        }
    }
}

// ---------------- kernel 0: zero output ----------------
__global__ void k_zero(float4* __restrict__ out) {
    out[blockIdx.x * 256 + threadIdx.x] = make_float4(0.f, 0.f, 0.f, 0.f);
}

// ---------------- kernel 1: gating (logits -> top2 -> 2-way softmax) ----------------
__global__ __launch_bounds__(256) void k_gate(const float* __restrict__ X,
                                              const float* __restrict__ Wg,
                                              const float* __restrict__ bg) {
    int n = blockIdx.x, tid = threadIdx.x;
    float acc[8] = {0.f, 0.f, 0.f, 0.f, 0.f, 0.f, 0.f, 0.f};
    const float* xr = X + (size_t)n * kD;
    for (int dd = tid; dd < kD; dd += 256) {
        float x = xr[dd];
        float4 w0 = *(const float4*)(Wg + dd * 8);
        float4 w1 = *(const float4*)(Wg + dd * 8 + 4);
        acc[0] += x * w0.x; acc[1] += x * w0.y; acc[2] += x * w0.z; acc[3] += x * w0.w;
        acc[4] += x * w1.x; acc[5] += x * w1.y; acc[6] += x * w1.z; acc[7] += x * w1.w;
    }
    __shared__ float red[8][256];
#pragma unroll
    for (int j = 0; j < 8; j++) red[j][tid] = acc[j];
    __syncthreads();
    for (int s = 128; s > 0; s >>= 1) {
        if (tid < s) {
#pragma unroll
            for (int j = 0; j < 8; j++) red[j][tid] += red[j][tid + s];
        }
        __syncthreads();
    }
    if (tid == 0) {
        float l[8];
#pragma unroll
        for (int j = 0; j < 8; j++) l[j] = red[j][0] + bg[j];
        int i1 = 0;
#pragma unroll
        for (int j = 1; j < 8; j++) if (l[j] > l[i1]) i1 = j;
        int i2 = -1; float best = -1e30f;
#pragma unroll
        for (int j = 0; j < 8; j++) if (j != i1 && l[j] > best) { best = l[j]; i2 = j; }
        float e = expf(l[i2] - l[i1]);         // <= 1
        float a1 = 1.0f / (1.0f + e);
        d_gidx[2 * n]     = i1 + 1;
        d_gidx[2 * n + 1] = i2 + 1;
        d_galpha[2 * n]     = a1;
        d_galpha[2 * n + 1] = e * a1;
    }
}

// ---------------- kernel 2: build per-(b,m) token lists (stable, time order) ----------------
__global__ void k_segbuild() {
    int seg = blockIdx.x;
    int b = seg / kMP1, m = seg % kMP1;
    int lane = threadIdx.x;
    int base = seg * kSEGCAP;
    if (m == 0) {
        for (int p = lane; p < kT; p += 32) {
            d_segtok[base + p] = p;
            d_segalpha[base + p] = 1.0f;
        }
        if (lane == 0) d_segcnt[seg] = kT;
        return;
    }
    int cnt = 0;
    for (int t0 = 0; t0 < kT; t0 += 32) {
        int t = t0 + lane;
        int n = t * kB + b;
        int i1 = d_gidx[2 * n], i2 = d_gidx[2 * n + 1];
        bool pred = (i1 == m) || (i2 == m);
        unsigned mask = __ballot_sync(0xffffffffu, pred);
        int rank = __popc(mask & ((1u << lane) - 1u));
        if (pred) {
            int pos = cnt + rank;
            d_segtok[base + pos] = t;
            d_segalpha[base + pos] = (i1 == m) ? d_galpha[2 * n] : d_galpha[2 * n + 1];
        }
        cnt += __popc(mask);
    }
    if (lane == 0) d_segcnt[seg] = cnt;
}

// ---------------- kernel 3: Q projection (dense 16384x1024x64 GEMM) ----------------
__global__ __launch_bounds__(256) void k_qproj(const float* __restrict__ X,
                                               const float* __restrict__ Wq,
                                               const float* __restrict__ bq) {
    __shared__ float Xs[32 * 64];   // [kk][row]
    __shared__ float Ws[32 * 64];   // [kk][col]
    int tid = threadIdx.x;
    int ty = tid >> 4, tx = tid & 15;
    int r0 = ty * 4, c0 = tx * 4;
    int rowBase = blockIdx.x * 64;
    float acc[4][4] = {};
    for (int dd0 = 0; dd0 < kD; dd0 += 32) {
#pragma unroll
        for (int it = 0; it < 2; it++) {
            int idx = it * 256 + tid;
            int row = idx >> 3, kq = (idx & 7) * 4;
            float4 xv = *(const float4*)(X + (size_t)(rowBase + row) * kD + dd0 + kq);
            Xs[(kq + 0) * 64 + row] = xv.x;
            Xs[(kq + 1) * 64 + row] = xv.y;
            Xs[(kq + 2) * 64 + row] = xv.z;
            Xs[(kq + 3) * 64 + row] = xv.w;
            int kk = idx >> 4, j4 = (idx & 15) * 4;
            *(float4*)&Ws[kk * 64 + j4] = *(const float4*)(Wq + (size_t)(dd0 + kk) * kHD + j4);
        }
        __syncthreads();
#pragma unroll 8
        for (int kk = 0; kk < 32; kk++) {
            float4 xv = *(float4*)&Xs[kk * 64 + r0];
            float4 wv = *(float4*)&Ws[kk * 64 + c0];
            outer4x4(acc, xv, wv);
        }
        __syncthreads();
    }
    float4 bb = *(const float4*)(bq + c0);
    float bv[4] = {bb.x, bb.y, bb.z, bb.w};
#pragma unroll
    for (int a = 0; a < 4; a++) {
        int n = rowBase + r0 + a;
        float4 o = make_float4(acc[a][0] + bv[0], acc[a][1] + bv[1],
                               acc[a][2] + bv[2], acc[a][3] + bv[3]);
        *(float4*)&d_Q[(size_t)n * kHD + c0] = o;
    }
}

// ---------------- kernel 4: gathered K/V projections per segment ----------------
__global__ __launch_bounds__(256) void k_kvproj(const float* __restrict__ X,
                                                const float* __restrict__ Wk,
                                                const float* __restrict__ bk,
                                                const float* __restrict__ Wv,
                                                const float* __restrict__ bv) {
    int seg = blockIdx.y;
    int cnt = d_segcnt[seg];
    int tileBase = blockIdx.x * 64;
    if (tileBase >= cnt) return;
    int L = min(64, cnt - tileBase);
    int b = seg / kMP1, m = seg % kMP1;

    __shared__ float Xs[32 * 64];    // [kk][row]
    __shared__ float Wks[32 * 64];   // [kk][col]
    __shared__ float Wvs[32 * 64];
    __shared__ int rowN[64];

    int tid = threadIdx.x;
    int ty = tid >> 4, tx = tid & 15;
    int r0 = ty * 4, c0 = tx * 4;

    if (tid < 64) {
        int n = -1;
        if (tid < L) {
            int t = d_segtok[seg * kSEGCAP + tileBase + tid];
            n = t * kB + b;
        }
        rowN[tid] = n;
    }
    __syncthreads();

    float accK[4][4] = {}, accV[4][4] = {};
    const float* WkBase = Wk + m * kHD;
    const float* WvBase = Wv + m * kHD;

    for (int dd0 = 0; dd0 < kD; dd0 += 32) {
#pragma unroll
        for (int it = 0; it < 2; it++) {
            int idx = it * 256 + tid;
            int row = idx >> 3, kq = (idx & 7) * 4;
            float4 xv = make_float4(0.f, 0.f, 0.f, 0.f);
            int n = rowN[row];
            if (n >= 0) xv = *(const float4*)(X + (size_t)n * kD + dd0 + kq);
            Xs[(kq + 0) * 64 + row] = xv.x;
            Xs[(kq + 1) * 64 + row] = xv.y;
            Xs[(kq + 2) * 64 + row] = xv.z;
            Xs[(kq + 3) * 64 + row] = xv.w;
            int kk = idx >> 4, j4 = (idx & 15) * 4;
            *(float4*)&Wks[kk * 64 + j4] =
                *(const float4*)(WkBase + (size_t)(dd0 + kk) * kWKSTRIDE + j4);
            *(float4*)&Wvs[kk * 64 + j4] =
                *(const float4*)(WvBase + (size_t)(dd0 + kk) * kWKSTRIDE + j4);
        }
        __syncthreads();
#pragma unroll 4
        for (int kk = 0; kk < 32; kk++) {
            float4 xv = *(float4*)&Xs[kk * 64 + r0];
            float4 wk = *(float4*)&Wks[kk * 64 + c0];
            float4 wv = *(float4*)&Wvs[kk * 64 + c0];
            outer4x4(accK, xv, wk);
            outer4x4(accV, xv, wv);
        }
        __syncthreads();
    }

    float4 bk4 = *(const float4*)(bk + m * kHD + c0);
    float4 bv4 = *(const float4*)(bv + m * kHD + c0);
    float bka[4] = {bk4.x, bk4.y, bk4.z, bk4.w};
    float bva[4] = {bv4.x, bv4.y, bv4.z, bv4.w};
#pragma unroll
    for (int a = 0; a < 4; a++) {
        int r = r0 + a;
        if (r < L) {
            size_t p = ((size_t)seg * kSEGCAP + tileBase + r) * kHD + c0;
            float4 ok = make_float4(accK[a][0] + bka[0], accK[a][1] + bka[1],
                                    accK[a][2] + bka[2], accK[a][3] + bka[3]);
            float4 ov = make_float4(accV[a][0] + bva[0], accV[a][1] + bva[1],
                                    accV[a][2] + bva[2], accV[a][3] + bva[3]);
            *(float4*)&d_K[p] = ok;
            *(float4*)&d_V[p] = ov;
        }
    }
}

// ---------------- kernel 5: per-chunk S = K^T V ----------------
__global__ __launch_bounds__(256) void k_chunkS() {
    int seg = blockIdx.y, c = blockIdx.x;
    int cnt = d_segcnt[seg];
    if (c * kCH >= cnt) return;
    int L = min(kCH, cnt - c * kCH);

    __shared__ float Ks[64 * 64];   // [r][i]
    __shared__ float Vs[64 * 64];   // [r][j]
    int tid = threadIdx.x;
    int ty = tid >> 4, tx = tid & 15;
    int i0 = ty * 4, j0 = tx * 4;
    size_t rowBase = (size_t)seg * kSEGCAP + c * kCH;

#pragma unroll
    for (int it = 0; it < 4; it++) {
        int idx = it * 256 + tid;
        int r = idx >> 4, j4 = (idx & 15) * 4;
        float4 kv = make_float4(0.f, 0.f, 0.f, 0.f), vv = kv;
        if (r < L) {
            kv = *(const float4*)&d_K[(rowBase + r) * kHD + j4];
            vv = *(const float4*)&d_V[(rowBase + r) * kHD + j4];
        }
        *(float4*)&Ks[r * 64 + j4] = kv;
        *(float4*)&Vs[r * 64 + j4] = vv;
    }
    __syncthreads();

    float acc[4][4] = {};
#pragma unroll 8
    for (int r = 0; r < 64; r++) {
        float4 kv = *(float4*)&Ks[r * 64 + i0];
        float4 vv = *(float4*)&Vs[r * 64 + j0];
        outer4x4(acc, kv, vv);
    }

    float* Sp = &d_CS[(size_t)(seg * kMAXCH + c) * 4096];
#pragma unroll
    for (int a = 0; a < 4; a++) {
        float4 o = make_float4(acc[a][0], acc[a][1], acc[a][2], acc[a][3]);
        *(float4*)&Sp[(i0 + a) * 64 + j0] = o;
    }
}

// ---------------- kernel 6: sequential prefix over chunks -> M_start (in place) ----------------
__global__ __launch_bounds__(256) void k_prefix(const float* __restrict__ M0) {
    int seg = blockIdx.x, tid = threadIdx.x;
    int cnt = d_segcnt[seg];
    int nc = (cnt + kCH - 1) / kCH;
    float run[16];
#pragma unroll
    for (int q = 0; q < 16; q++) run[q] = M0[q * 256 + tid];
    for (int c = 0; c < nc; c++) {
        float* p = &d_CS[(size_t)(seg * kMAXCH + c) * 4096];
#pragma unroll
        for (int q = 0; q < 16; q++) {
            float s = p[q * 256 + tid];
            p[q * 256 + tid] = run[q];   // M_start for this chunk
            run[q] += s;
        }
    }
}

// ---------------- kernel 7: O = tril(QK^T)V + Q M_start, weighted scatter ----------------
__global__ __launch_bounds__(256) void k_out(float* __restrict__ out) {
    int seg = blockIdx.y, c = blockIdx.x;
    int cnt = d_segcnt[seg];
    if (c * kCH >= cnt) return;
    int b = seg / kMP1;

    __shared__ float Qs[64 * 64];   // [r][j]
    __shared__ float KA[64 * 64];   // K [r][j], then masked A [r][cc]
    __shared__ float Vs[64 * 64];   // [r][j]

    int tid = threadIdx.x;
    int ty = tid >> 4, tx = tid & 15;
    int r0 = ty * 4;
    size_t rowBase = (size_t)seg * kSEGCAP + c * kCH;
    int segBase = seg * kSEGCAP;

#pragma unroll
    for (int it = 0; it < 4; it++) {
        int idx = it * 256 + tid;
        int r = idx >> 4, j4 = (idx & 15) * 4;
        float4 qv = make_float4(0.f, 0.f, 0.f, 0.f), kv = qv, vv = qv;
        int pos = c * kCH + r;
        if (pos < cnt) {
            int t = d_segtok[segBase + pos];
            int n = t * kB + b;
            qv = *(const float4*)&d_Q[(size_t)n * kHD + j4];
            kv = *(const float4*)&d_K[(rowBase + r) * kHD + j4];
            vv = *(const float4*)&d_V[(rowBase + r) * kHD + j4];
        }
        *(float4*)&Qs[r * 64 + j4] = qv;
        *(float4*)&KA[r * 64 + j4] = kv;
        *(float4*)&Vs[r * 64 + j4] = vv;
    }
    __syncthreads();

    // Phase A: A[r][cc] = Q[r] . K[cc]
    int cc0 = tx * 4;
    float aacc[4][4] = {};
#pragma unroll 4
    for (int j = 0; j < 64; j += 4) {
        float4 q[4], k[4];
#pragma unroll
        for (int a = 0; a < 4; a++) q[a] = *(float4*)&Qs[(r0 + a) * 64 + j];
#pragma unroll
        for (int u = 0; u < 4; u++) k[u] = *(float4*)&KA[(cc0 + u) * 64 + j];
#pragma unroll
        for (int a = 0; a < 4; a++)
#pragma unroll
            for (int u = 0; u < 4; u++) aacc[a][u] += dot4(q[a], k[u]);
    }
    __syncthreads();
    // write masked (inclusive lower-triangular) A over KA
#pragma unroll
    for (int a = 0; a < 4; a++) {
        int r = r0 + a;
#pragma unroll
        for (int u = 0; u < 4; u++) {
            int cc = cc0 + u;
            KA[r * 64 + cc] = (cc <= r) ? aacc[a][u] : 0.f;
        }
    }
    __syncthreads();

    // Phase O: O = A V + Q M_start
    int j0 = tx * 4;
    float oacc[4][4] = {};
#pragma unroll 4
    for (int cc = 0; cc < 64; cc += 4) {
        float4 arow[4], vrow[4];
#pragma unroll
        for (int a = 0; a < 4; a++) arow[a] = *(float4*)&KA[(r0 + a) * 64 + cc];
#pragma unroll
        for (int u = 0; u < 4; u++) vrow[u] = *(float4*)&Vs[(cc + u) * 64 + j0];
        gemm4x4(oacc, arow, vrow);
    }
    const float* Mg = &d_CS[(size_t)(seg * kMAXCH + c) * 4096];
#pragma unroll 4
    for (int i = 0; i < 64; i += 4) {
        float4 qrow[4], mrow[4];
#pragma unroll
        for (int a = 0; a < 4; a++) qrow[a] = *(float4*)&Qs[(r0 + a) * 64 + i];
#pragma unroll
        for (int u = 0; u < 4; u++) mrow[u] = *(const float4*)&Mg[(i + u) * 64 + j0];
        gemm4x4(oacc, qrow, mrow);
    }

    // scatter: out[t,b,:] += alpha * O[r,:]
#pragma unroll
    for (int a = 0; a < 4; a++) {
        int r = r0 + a;
        int pos = c * kCH + r;
        if (pos < cnt) {
            int t = d_segtok[segBase + pos];
            float al = d_segalpha[segBase + pos];
            float* op = out + ((size_t)t * kB + b) * kHD + j0;
            atomicAdd(op + 0, al * oacc[a][0]);
            atomicAdd(op + 1, al * oacc[a][1]);
            atomicAdd(op + 2, al * oacc[a][2]);
            atomicAdd(op + 3, al * oacc[a][3]);
        }
    }
}

// ---------------- launch ----------------
extern "C" void kernel_launch(void* const* d_in, const int* in_sizes, int n_in,
                              void* d_out, int out_size) {
    const float* X  = (const float*)d_in[0];
    const float* M0 = (const float*)d_in[1];
    const float* Wq = (const float*)d_in[2];
    const float* bq = (const float*)d_in[3];
    const float* Wk = (const float*)d_in[4];
    const float* bk = (const float*)d_in[5];
    const float* Wv = (const float*)d_in[6];
    const float* bv = (const float*)d_in[7];
    const float* Wg = (const float*)d_in[8];
    const float* bg = (const float*)d_in[9];
    float* out = (float*)d_out;

    k_zero<<<kNTOK * kHD / (256 * 4), 256>>>((float4*)out);
    k_gate<<<kNTOK, 256>>>(X, Wg, bg);
    k_segbuild<<<kNSEG, 32>>>();
    k_qproj<<<kNTOK / 64, 256>>>(X, Wq, bq);
    k_kvproj<<<dim3(kMAXCH, kNSEG), 256>>>(X, Wk, bk, Wv, bv);
    k_chunkS<<<dim3(kMAXCH, kNSEG), 256>>>();
    k_prefix<<<kNSEG, 256>>>(M0);
    k_out<<<dim3(kMAXCH, kNSEG), 256>>>(out);
}